// round 2
// baseline (speedup 1.0000x reference)
#include <cuda_runtime.h>

// Problem constants
#define NB 2
#define NS 2048
#define NC 1024
#define NH 16
#define ND 64

// Attention tiling
#define BM 64
#define BN 64
#define STR 68   // padded smem row stride (floats), 16B-aligned

// Scratch for attention output before projection: [B,S,C] fp32 = 16 MB
__device__ float g_attn[(size_t)NB * NS * NC];

// ---------------------------------------------------------------------------
// Kernel 1: flash-attention per (q-tile, head, batch).
// grid = (S/BM, H, B), block = 256 (16x16 threads, 4x4 micro-tile)
// ---------------------------------------------------------------------------
__global__ void __launch_bounds__(256) attn_kernel(
    const float* __restrict__ qg, const float* __restrict__ kg,
    const float* __restrict__ vg, const unsigned int* __restrict__ maskg)
{
    extern __shared__ float sm[];
    float* Qt    = sm;                 // [ND][STR]
    float* Kt    = Qt + ND * STR;      // [ND][STR]
    float* Vs    = Kt + ND * STR;      // [BN][STR]
    float* Pt    = Vs + BN * STR;      // [BN][STR]
    float* biasS = Pt + BN * STR;      // [BN]
    float* mrow  = biasS + BN;         // [BM]
    float* lrow  = mrow + BM;          // [BM]
    float* rsc   = lrow + BM;          // [BM]

    const int tid = threadIdx.x;
    const int tx = tid & 15;
    const int ty = tid >> 4;
    const int b  = blockIdx.z;
    const int h  = blockIdx.y;
    const int q0 = blockIdx.x * BM;

    const float* qbase = qg + (size_t)b * NS * NC + h * ND;
    const float* kbase = kg + (size_t)b * NS * NC + h * ND;
    const float* vbase = vg + (size_t)b * NS * NC + h * ND;

    // ---- load Q tile, transposed + pre-scaled by 1/sqrt(D) ----
    const float qscale = 0.125f;  // D = 64
    {
        const int c4 = tid & 15;
        const int r0 = tid >> 4;
        #pragma unroll
        for (int p = 0; p < 4; p++) {
            const int r = r0 + p * 16;
            float4 val = *reinterpret_cast<const float4*>(
                qbase + (size_t)(q0 + r) * NC + c4 * 4);
            Qt[(c4 * 4 + 0) * STR + r] = val.x * qscale;
            Qt[(c4 * 4 + 1) * STR + r] = val.y * qscale;
            Qt[(c4 * 4 + 2) * STR + r] = val.z * qscale;
            Qt[(c4 * 4 + 3) * STR + r] = val.w * qscale;
        }
    }
    if (tid < BM) { mrow[tid] = -3.0e38f; lrow[tid] = 0.0f; }

    float o[4][4] = {};

    for (int n0 = 0; n0 < NS; n0 += BN) {
        // ---- load K (transposed) and V (row-major) tiles + mask bias ----
        {
            const int c4 = tid & 15;
            const int r0 = tid >> 4;
            #pragma unroll
            for (int p = 0; p < 4; p++) {
                const int r = r0 + p * 16;
                float4 kv = *reinterpret_cast<const float4*>(
                    kbase + (size_t)(n0 + r) * NC + c4 * 4);
                Kt[(c4 * 4 + 0) * STR + r] = kv.x;
                Kt[(c4 * 4 + 1) * STR + r] = kv.y;
                Kt[(c4 * 4 + 2) * STR + r] = kv.z;
                Kt[(c4 * 4 + 3) * STR + r] = kv.w;
                float4 vv = *reinterpret_cast<const float4*>(
                    vbase + (size_t)(n0 + r) * NC + c4 * 4);
                *reinterpret_cast<float4*>(&Vs[r * STR + c4 * 4]) = vv;
            }
        }
        // mask is a bool promoted to a 4-byte dtype (int32 0/1 or float32
        // 0.0/1.0). Either way: 32-bit word != 0 <=> True.
        if (tid < BN)
            biasS[tid] = (maskg[b * NS + n0 + tid] != 0u) ? 0.0f : -1.0e12f;
        __syncthreads();

        // ---- GEMM1: S[row][col] = (Q*scale) . K over D ----
        float s[4][4] = {};
        #pragma unroll 8
        for (int kk = 0; kk < ND; kk++) {
            float4 a  = *reinterpret_cast<const float4*>(&Qt[kk * STR + ty * 4]);
            float4 bb = *reinterpret_cast<const float4*>(&Kt[kk * STR + tx * 4]);
            const float av[4] = {a.x, a.y, a.z, a.w};
            const float bv[4] = {bb.x, bb.y, bb.z, bb.w};
            #pragma unroll
            for (int i = 0; i < 4; i++)
                #pragma unroll
                for (int j = 0; j < 4; j++)
                    s[i][j] += av[i] * bv[j];
        }
        // write scores transposed: Pt[col][row]
        #pragma unroll
        for (int j = 0; j < 4; j++) {
            float4 w = make_float4(s[0][j], s[1][j], s[2][j], s[3][j]);
            *reinterpret_cast<float4*>(&Pt[(tx * 4 + j) * STR + ty * 4]) = w;
        }
        __syncthreads();

        // ---- online softmax: thread (row = tid/4, part = tid%4) owns 16 cols
        {
            const int row  = tid >> 2;
            const int part = tid & 3;
            float vmax = -3.0e38f;
            #pragma unroll
            for (int t2 = 0; t2 < 16; t2++) {
                const int n = part * 16 + t2;
                vmax = fmaxf(vmax, Pt[n * STR + row] + biasS[n]);
            }
            vmax = fmaxf(vmax, __shfl_xor_sync(0xffffffffu, vmax, 1));
            vmax = fmaxf(vmax, __shfl_xor_sync(0xffffffffu, vmax, 2));
            const float mold = mrow[row];
            const float mnew = fmaxf(mold, vmax);
            float lsum = 0.0f;
            #pragma unroll
            for (int t2 = 0; t2 < 16; t2++) {
                const int n = part * 16 + t2;
                float p = __expf(Pt[n * STR + row] + biasS[n] - mnew);
                lsum += p;
                Pt[n * STR + row] = p;
            }
            lsum += __shfl_xor_sync(0xffffffffu, lsum, 1);
            lsum += __shfl_xor_sync(0xffffffffu, lsum, 2);
            if (part == 0) {
                const float sc = __expf(mold - mnew);
                rsc[row]  = sc;
                lrow[row] = lrow[row] * sc + lsum;
                mrow[row] = mnew;
            }
        }
        __syncthreads();

        // ---- rescale accumulator, then GEMM2: O += P @ V ----
        #pragma unroll
        for (int i = 0; i < 4; i++) {
            const float sc = rsc[ty * 4 + i];
            #pragma unroll
            for (int j = 0; j < 4; j++) o[i][j] *= sc;
        }
        #pragma unroll 8
        for (int n = 0; n < BN; n++) {
            float4 a  = *reinterpret_cast<const float4*>(&Pt[n * STR + ty * 4]);
            float4 bb = *reinterpret_cast<const float4*>(&Vs[n * STR + tx * 4]);
            const float av[4] = {a.x, a.y, a.z, a.w};
            const float bv[4] = {bb.x, bb.y, bb.z, bb.w};
            #pragma unroll
            for (int i = 0; i < 4; i++)
                #pragma unroll
                for (int j = 0; j < 4; j++)
                    o[i][j] += av[i] * bv[j];
        }
        __syncthreads();
    }

    // ---- epilogue: divide by row sum, write to scratch ----
    #pragma unroll
    for (int i = 0; i < 4; i++) {
        const int row = ty * 4 + i;
        const float inv = 1.0f / lrow[row];
        float4 w = make_float4(o[i][0] * inv, o[i][1] * inv,
                               o[i][2] * inv, o[i][3] * inv);
        *reinterpret_cast<float4*>(
            &g_attn[((size_t)b * NS + q0 + row) * NC + h * ND + tx * 4]) = w;
    }
}

// ---------------------------------------------------------------------------
// Kernel 2: output projection  out[m][n] = sum_k attn[m][k] * W[n][k]
// M = B*S = 4096, N = K = 1024. Tiled SGEMM, 64x64x16, 4x4 micro-tile.
// ---------------------------------------------------------------------------
__global__ void __launch_bounds__(256) proj_kernel(
    const float* __restrict__ W, float* __restrict__ out)
{
    __shared__ float At[16][STR];
    __shared__ float Wt[16][STR];

    const int tid = threadIdx.x;
    const int tx = tid & 15;
    const int ty = tid >> 4;
    const int n0 = blockIdx.x * 64;
    const int m0 = blockIdx.y * 64;

    float acc[4][4] = {};

    const int r  = tid >> 2;   // 0..63 tile row
    const int k4 = tid & 3;    // 0..3  k float4 slot

    for (int k0 = 0; k0 < NC; k0 += 16) {
        float4 av = *reinterpret_cast<const float4*>(
            g_attn + (size_t)(m0 + r) * NC + k0 + k4 * 4);
        At[k4 * 4 + 0][r] = av.x;
        At[k4 * 4 + 1][r] = av.y;
        At[k4 * 4 + 2][r] = av.z;
        At[k4 * 4 + 3][r] = av.w;
        float4 wv = *reinterpret_cast<const float4*>(
            W + (size_t)(n0 + r) * NC + k0 + k4 * 4);
        Wt[k4 * 4 + 0][r] = wv.x;
        Wt[k4 * 4 + 1][r] = wv.y;
        Wt[k4 * 4 + 2][r] = wv.z;
        Wt[k4 * 4 + 3][r] = wv.w;
        __syncthreads();

        #pragma unroll
        for (int kk = 0; kk < 16; kk++) {
            float4 a  = *reinterpret_cast<const float4*>(&At[kk][ty * 4]);
            float4 bb = *reinterpret_cast<const float4*>(&Wt[kk][tx * 4]);
            const float avv[4] = {a.x, a.y, a.z, a.w};
            const float bvv[4] = {bb.x, bb.y, bb.z, bb.w};
            #pragma unroll
            for (int i = 0; i < 4; i++)
                #pragma unroll
                for (int j = 0; j < 4; j++)
                    acc[i][j] += avv[i] * bvv[j];
        }
        __syncthreads();
    }

    #pragma unroll
    for (int i = 0; i < 4; i++) {
        float4 w = make_float4(acc[i][0], acc[i][1], acc[i][2], acc[i][3]);
        *reinterpret_cast<float4*>(
            &out[(size_t)(m0 + ty * 4 + i) * NC + n0 + tx * 4]) = w;
    }
}

// ---------------------------------------------------------------------------
extern "C" void kernel_launch(void* const* d_in, const int* in_sizes, int n_in,
                              void* d_out, int out_size)
{
    const float* q = (const float*)d_in[0];
    const float* k = (const float*)d_in[1];
    const float* v = (const float*)d_in[2];
    const unsigned int* mask = (const unsigned int*)d_in[3];
    const float* W = (const float*)d_in[4];
    float* out = (float*)d_out;

    const size_t smem_bytes =
        (size_t)(4 * ND * STR + BN + 3 * BM) * sizeof(float);  // ~70.7 KB

    cudaFuncSetAttribute((const void*)attn_kernel,
                         cudaFuncAttributeMaxDynamicSharedMemorySize,
                         (int)smem_bytes);

    attn_kernel<<<dim3(NS / BM, NH, NB), 256, smem_bytes>>>(q, k, v, mask);
    proj_kernel<<<dim3(NC / 64, (NB * NS) / 64), 256>>>(W, out);
}

// round 4
// speedup vs baseline: 2.7690x; 2.7690x over previous
#include <cuda_runtime.h>
#include <cuda_bf16.h>
#include <cstdint>

#define NB 2
#define NS 2048
#define NC 1024
#define NH 16
#define ND 64
#define BM 128
#define BN 64
#define NTILE (NS/BN)

// ---- scratch (__device__ globals: allowed) ----
__device__ __nv_bfloat16 g_qhi[(size_t)NB*NH*NS*ND];
__device__ __nv_bfloat16 g_qlo[(size_t)NB*NH*NS*ND];
__device__ __nv_bfloat16 g_khi[(size_t)NB*NH*NS*ND];
__device__ __nv_bfloat16 g_klo[(size_t)NB*NH*NS*ND];
__device__ __nv_bfloat16 g_vthi[(size_t)NB*NH*ND*NS];  // V transposed [b,h,d,s]
__device__ __nv_bfloat16 g_vtlo[(size_t)NB*NH*ND*NS];
__device__ __nv_bfloat16 g_whi[(size_t)NC*NC];
__device__ __nv_bfloat16 g_wlo[(size_t)NC*NC];
__device__ __nv_bfloat16 g_ahi[(size_t)NB*NS*NC];
__device__ __nv_bfloat16 g_alo[(size_t)NB*NS*NC];
__device__ float g_bias[(size_t)NB*NS];

// ---------------- helpers ----------------
__device__ __forceinline__ uint32_t smem_u32(const void* p){
    uint32_t a;
    asm("{ .reg .u64 t; cvta.to.shared.u64 t, %1; cvt.u32.u64 %0, t; }"
        : "=r"(a) : "l"(p));
    return a;
}
// 128-byte-row swizzle: offset for (row, byteInRow)
#define SWZ(r, byte) ((uint32_t)((r)*128 + ((byte) ^ (((r)&7)<<4))))

// split two floats into packed bf16x2 hi and residual lo
__device__ __forceinline__ void split2(float x, float y, uint32_t& hi, uint32_t& lo){
    __nv_bfloat162 h = __float22bfloat162_rn(make_float2(x, y));
    float2 hf = __bfloat1622float2(h);
    __nv_bfloat162 l = __float22bfloat162_rn(make_float2(x - hf.x, y - hf.y));
    hi = *reinterpret_cast<uint32_t*>(&h);
    lo = *reinterpret_cast<uint32_t*>(&l);
}
__device__ __forceinline__ void split4(float4 v, uint2& hi, uint2& lo){
    split2(v.x, v.y, hi.x, lo.x);
    split2(v.z, v.w, hi.y, lo.y);
}

// ldmatrix x4 for A-fragment (m16 x k16): tiles {m0k0, m8k0, m0k8, m8k8}
__device__ __forceinline__ void ldsmA(uint32_t r[4], uint32_t region, int row0, int byte0){
    const int lane = threadIdx.x & 31;
    const int t = lane >> 3, rr = lane & 7;
    const int row = row0 + rr + ((t & 1) << 3);
    const int byte = byte0 + ((t >> 1) << 4);
    uint32_t addr = region + SWZ(row, byte);
    asm volatile("ldmatrix.sync.aligned.m8n8.x4.shared.b16 {%0,%1,%2,%3}, [%4];"
        : "=r"(r[0]), "=r"(r[1]), "=r"(r[2]), "=r"(r[3]) : "r"(addr));
}
// ldmatrix x4 for two B-fragments (n8 x k16 each): tiles {n0k0, n0k8, n8k0, n8k8}
__device__ __forceinline__ void ldsmB(uint32_t r[4], uint32_t region, int row0, int byte0){
    const int lane = threadIdx.x & 31;
    const int t = lane >> 3, rr = lane & 7;
    const int row = row0 + rr + ((t >> 1) << 3);
    const int byte = byte0 + ((t & 1) << 4);
    uint32_t addr = region + SWZ(row, byte);
    asm volatile("ldmatrix.sync.aligned.m8n8.x4.shared.b16 {%0,%1,%2,%3}, [%4];"
        : "=r"(r[0]), "=r"(r[1]), "=r"(r[2]), "=r"(r[3]) : "r"(addr));
}
__device__ __forceinline__ void mma16816(float c[4], const uint32_t a[4],
                                         uint32_t b0, uint32_t b1){
    asm volatile(
        "mma.sync.aligned.m16n8k16.row.col.f32.bf16.bf16.f32 "
        "{%0,%1,%2,%3}, {%4,%5,%6,%7}, {%8,%9}, {%0,%1,%2,%3};"
        : "+f"(c[0]), "+f"(c[1]), "+f"(c[2]), "+f"(c[3])
        : "r"(a[0]), "r"(a[1]), "r"(a[2]), "r"(a[3]), "r"(b0), "r"(b1));
}

// ===========================================================================
// Prepass A: per (b, h, 64-row s-tile): convert Q,K -> hi/lo bf16 packed
// [b,h,s,d]; V -> transposed hi/lo [b,h,d,s]. Q pre-scaled by 1/sqrt(D).
// ===========================================================================
__global__ void __launch_bounds__(256) qkvconv(
    const float* __restrict__ q, const float* __restrict__ k,
    const float* __restrict__ v)
{
    __shared__ float sv[64][68];
    const int tid = threadIdx.x;
    const int b = blockIdx.z, h = blockIdx.y, s0 = blockIdx.x * 64;
    const size_t inb  = ((size_t)b * NS + s0) * NC + h * ND;
    const size_t outb = (((size_t)b * NH + h) * NS + s0) * ND;

    #pragma unroll
    for (int p = 0; p < 4; p++){
        int idx = tid + p * 256;         // 0..1023
        int r = idx >> 4, c4 = idx & 15;
        size_t src = inb + (size_t)r * NC + c4 * 4;
        size_t dst = outb + r * ND + c4 * 4;
        float4 xq = *reinterpret_cast<const float4*>(q + src);
        xq.x *= 0.125f; xq.y *= 0.125f; xq.z *= 0.125f; xq.w *= 0.125f;
        uint2 hi, lo; split4(xq, hi, lo);
        *reinterpret_cast<uint2*>(g_qhi + dst) = hi;
        *reinterpret_cast<uint2*>(g_qlo + dst) = lo;
        float4 xk = *reinterpret_cast<const float4*>(k + src);
        split4(xk, hi, lo);
        *reinterpret_cast<uint2*>(g_khi + dst) = hi;
        *reinterpret_cast<uint2*>(g_klo + dst) = lo;
        float4 xv = *reinterpret_cast<const float4*>(v + src);
        *reinterpret_cast<float4*>(&sv[r][c4 * 4]) = xv;
    }
    __syncthreads();
    // transpose V out: thread -> (d = tid%64, 16 s-values starting at sh)
    const int d = tid & 63, sh = (tid >> 6) * 16;
    uint32_t hi8[8], lo8[8];
    #pragma unroll
    for (int i = 0; i < 8; i++)
        split2(sv[sh + 2*i][d], sv[sh + 2*i + 1][d], hi8[i], lo8[i]);
    size_t voff = (((size_t)b * NH + h) * ND + d) * NS + s0 + sh;
    reinterpret_cast<uint4*>(g_vthi + voff)[0] = make_uint4(hi8[0],hi8[1],hi8[2],hi8[3]);
    reinterpret_cast<uint4*>(g_vthi + voff)[1] = make_uint4(hi8[4],hi8[5],hi8[6],hi8[7]);
    reinterpret_cast<uint4*>(g_vtlo + voff)[0] = make_uint4(lo8[0],lo8[1],lo8[2],lo8[3]);
    reinterpret_cast<uint4*>(g_vtlo + voff)[1] = make_uint4(lo8[4],lo8[5],lo8[6],lo8[7]);
}

// Prepass B: W -> hi/lo. Prepass C: mask -> additive bias.
__global__ void __launch_bounds__(256) wconv(const float* __restrict__ W){
    int i = blockIdx.x * 256 + threadIdx.x;
    float x = W[i];
    __nv_bfloat16 hi = __float2bfloat16_rn(x);
    g_whi[i] = hi;
    g_wlo[i] = __float2bfloat16_rn(x - __bfloat162float(hi));
}
__global__ void __launch_bounds__(256) biasconv(const unsigned int* __restrict__ mask){
    int i = blockIdx.x * 256 + threadIdx.x;
    g_bias[i] = (mask[i] != 0u) ? 0.0f : -1.0e12f;
}

// ---------------- attention smem offsets (bytes) ----------------
#define AQHI 0
#define AQLO 16384
#define AKHI 32768
#define AKLO 40960
#define AVHI 49152
#define AVLO 57344
#define ABIAS 65536
#define ASM_BYTES 65792

// ===========================================================================
// Attention: 256 threads = 8 warps; warp owns 16 q-rows x 64 key-cols.
// Split-bf16 3-MMA for both GEMMs; P stays in registers (C-frag == A-frag).
// No max subtraction => O accumulates across tiles with no rescaling.
// ===========================================================================
__global__ void __launch_bounds__(256, 1) attn_tc()
{
    extern __shared__ __align__(1024) char sm[];
    const uint32_t sb = smem_u32(sm);
    const int tid = threadIdx.x, lane = tid & 31, warp = tid >> 5;
    const int b = blockIdx.z, h = blockIdx.y, q0 = blockIdx.x * BM;

    const size_t qb  = (((size_t)b * NH + h) * NS + q0) * ND;
    const size_t kb  = ((size_t)b * NH + h) * NS * ND;
    const size_t vtb = ((size_t)b * NH + h) * (size_t)ND * NS;

    // Q tile -> smem (hi+lo), swizzled 128B rows
    #pragma unroll
    for (int p = 0; p < 4; p++){
        int idx = tid + p * 256;             // 0..1023
        int r = idx >> 3, ch = idx & 7;
        uint32_t off = SWZ(r, ch * 16);
        *reinterpret_cast<uint4*>(sm + AQHI + off) =
            *reinterpret_cast<const uint4*>(g_qhi + qb + (size_t)r * ND + ch * 8);
        *reinterpret_cast<uint4*>(sm + AQLO + off) =
            *reinterpret_cast<const uint4*>(g_qlo + qb + (size_t)r * ND + ch * 8);
    }
    __syncthreads();

    // Q A-fragments to registers (4 k16-chunks, hi+lo)
    uint32_t qh[4][4], ql[4][4];
    #pragma unroll
    for (int kc = 0; kc < 4; kc++){
        ldsmA(qh[kc], sb + AQHI, warp * 16, kc * 32);
        ldsmA(ql[kc], sb + AQLO, warp * 16, kc * 32);
    }

    float o[8][4] = {};
    float lsum0 = 0.f, lsum1 = 0.f;
    const float* biasf = reinterpret_cast<const float*>(sm + ABIAS);

    #pragma unroll 1
    for (int t = 0; t < NTILE; t++){
        const int n0 = t * BN;
        __syncthreads();
        #pragma unroll
        for (int p = 0; p < 2; p++){
            int idx = tid + p * 256;        // 0..511
            int r = idx >> 3, ch = idx & 7;
            uint32_t off = SWZ(r, ch * 16);
            *reinterpret_cast<uint4*>(sm + AKHI + off) =
                *reinterpret_cast<const uint4*>(g_khi + kb + (size_t)(n0 + r) * ND + ch * 8);
            *reinterpret_cast<uint4*>(sm + AKLO + off) =
                *reinterpret_cast<const uint4*>(g_klo + kb + (size_t)(n0 + r) * ND + ch * 8);
            *reinterpret_cast<uint4*>(sm + AVHI + off) =
                *reinterpret_cast<const uint4*>(g_vthi + vtb + (size_t)r * NS + n0 + ch * 8);
            *reinterpret_cast<uint4*>(sm + AVLO + off) =
                *reinterpret_cast<const uint4*>(g_vtlo + vtb + (size_t)r * NS + n0 + ch * 8);
        }
        if (tid < BN)
            reinterpret_cast<float*>(sm + ABIAS)[tid] = g_bias[(size_t)b * NS + n0 + tid];
        __syncthreads();

        // ---- GEMM1: S = Qhi*Khi + Qhi*Klo + Qlo*Khi ----
        float s[8][4] = {};
        #pragma unroll
        for (int term = 0; term < 3; term++){
            const uint32_t (*A)[4] = (term == 2) ? ql : qh;
            const uint32_t reg = (term == 1) ? (sb + AKLO) : (sb + AKHI);
            #pragma unroll
            for (int kc = 0; kc < 4; kc++){
                #pragma unroll
                for (int nbp = 0; nbp < 4; nbp++){
                    uint32_t bf[4];
                    ldsmB(bf, reg, nbp * 16, kc * 32);
                    mma16816(s[nbp * 2],     A[kc], bf[0], bf[1]);
                    mma16816(s[nbp * 2 + 1], A[kc], bf[2], bf[3]);
                }
            }
        }

        // ---- softmax in registers + split-bf16 pack into A-frags ----
        uint32_t ph[4][4], pl[4][4];
        #pragma unroll
        for (int nb = 0; nb < 8; nb++){
            float2 b2 = *reinterpret_cast<const float2*>(
                biasf + nb * 8 + (lane & 3) * 2);
            float e0 = __expf(s[nb][0] + b2.x);
            float e1 = __expf(s[nb][1] + b2.y);
            float e2 = __expf(s[nb][2] + b2.x);
            float e3 = __expf(s[nb][3] + b2.y);
            lsum0 += e0 + e1;
            lsum1 += e2 + e3;
            split2(e0, e1, ph[nb >> 1][(nb & 1) * 2 + 0], pl[nb >> 1][(nb & 1) * 2 + 0]);
            split2(e2, e3, ph[nb >> 1][(nb & 1) * 2 + 1], pl[nb >> 1][(nb & 1) * 2 + 1]);
        }

        // ---- GEMM2: O += Phi*Vhi + Phi*Vlo + Plo*Vhi ----
        #pragma unroll
        for (int term = 0; term < 3; term++){
            const uint32_t (*A)[4] = (term == 2) ? pl : ph;
            const uint32_t reg = (term == 1) ? (sb + AVLO) : (sb + AVHI);
            #pragma unroll
            for (int kc = 0; kc < 4; kc++){
                #pragma unroll
                for (int nbp = 0; nbp < 4; nbp++){
                    uint32_t bf[4];
                    ldsmB(bf, reg, nbp * 16, kc * 32);
                    mma16816(o[nbp * 2],     A[kc], bf[0], bf[1]);
                    mma16816(o[nbp * 2 + 1], A[kc], bf[2], bf[3]);
                }
            }
        }
    }

    // row sums complete within each quad
    lsum0 += __shfl_xor_sync(0xffffffffu, lsum0, 1);
    lsum0 += __shfl_xor_sync(0xffffffffu, lsum0, 2);
    lsum1 += __shfl_xor_sync(0xffffffffu, lsum1, 1);
    lsum1 += __shfl_xor_sync(0xffffffffu, lsum1, 2);
    const float inv0 = 1.0f / lsum0, inv1 = 1.0f / lsum1;

    // epilogue: write O/l as split bf16 hi/lo into [B,S,C] scratch
    const int row0 = q0 + warp * 16 + (lane >> 2);
    const int cbase = h * ND + (lane & 3) * 2;
    #pragma unroll
    for (int nb = 0; nb < 8; nb++){
        uint32_t hi, lo;
        size_t off0 = ((size_t)b * NS + row0) * NC + cbase + nb * 8;
        split2(o[nb][0] * inv0, o[nb][1] * inv0, hi, lo);
        *reinterpret_cast<uint32_t*>(g_ahi + off0) = hi;
        *reinterpret_cast<uint32_t*>(g_alo + off0) = lo;
        size_t off1 = off0 + (size_t)8 * NC;
        split2(o[nb][2] * inv1, o[nb][3] * inv1, hi, lo);
        *reinterpret_cast<uint32_t*>(g_ahi + off1) = hi;
        *reinterpret_cast<uint32_t*>(g_alo + off1) = lo;
    }
}

// ---------------- projection smem offsets ----------------
#define PAHI 0
#define PALO 16384
#define PWHI 32768
#define PWLO 40960
#define PSM_BYTES 49152

// ===========================================================================
// Projection: out[m][n] = sum_k A[m][k] * W[n][k], split-bf16 3-MMA.
// CTA: 128 m-rows x 64 n-cols, k in 16 chunks of 64.
// ===========================================================================
__global__ void __launch_bounds__(256, 2) proj_tc(float* __restrict__ out)
{
    extern __shared__ __align__(1024) char sm[];
    const uint32_t sb = smem_u32(sm);
    const int tid = threadIdx.x, lane = tid & 31, warp = tid >> 5;
    const int n0 = blockIdx.x * 64, m0 = blockIdx.y * 128;

    float o[8][4] = {};

    #pragma unroll 1
    for (int kc_o = 0; kc_o < 16; kc_o++){
        const int k0 = kc_o * 64;
        __syncthreads();
        #pragma unroll
        for (int p = 0; p < 4; p++){
            int idx = tid + p * 256;        // 0..1023 -> A rows
            int r = idx >> 3, ch = idx & 7;
            uint32_t off = SWZ(r, ch * 16);
            *reinterpret_cast<uint4*>(sm + PAHI + off) =
                *reinterpret_cast<const uint4*>(g_ahi + (size_t)(m0 + r) * NC + k0 + ch * 8);
            *reinterpret_cast<uint4*>(sm + PALO + off) =
                *reinterpret_cast<const uint4*>(g_alo + (size_t)(m0 + r) * NC + k0 + ch * 8);
        }
        #pragma unroll
        for (int p = 0; p < 2; p++){
            int idx = tid + p * 256;        // 0..511 -> W rows
            int r = idx >> 3, ch = idx & 7;
            uint32_t off = SWZ(r, ch * 16);
            *reinterpret_cast<uint4*>(sm + PWHI + off) =
                *reinterpret_cast<const uint4*>(g_whi + (size_t)(n0 + r) * NC + k0 + ch * 8);
            *reinterpret_cast<uint4*>(sm + PWLO + off) =
                *reinterpret_cast<const uint4*>(g_wlo + (size_t)(n0 + r) * NC + k0 + ch * 8);
        }
        __syncthreads();

        uint32_t ah[4][4], al[4][4];
        #pragma unroll
        for (int kc = 0; kc < 4; kc++){
            ldsmA(ah[kc], sb + PAHI, warp * 16, kc * 32);
            ldsmA(al[kc], sb + PALO, warp * 16, kc * 32);
        }
        #pragma unroll
        for (int term = 0; term < 3; term++){
            const uint32_t (*A)[4] = (term == 2) ? al : ah;
            const uint32_t reg = (term == 1) ? (sb + PWLO) : (sb + PWHI);
            #pragma unroll
            for (int kc = 0; kc < 4; kc++){
                #pragma unroll
                for (int nbp = 0; nbp < 4; nbp++){
                    uint32_t bf[4];
                    ldsmB(bf, reg, nbp * 16, kc * 32);
                    mma16816(o[nbp * 2],     A[kc], bf[0], bf[1]);
                    mma16816(o[nbp * 2 + 1], A[kc], bf[2], bf[3]);
                }
            }
        }
    }

    const int row0 = m0 + warp * 16 + (lane >> 2);
    const int cb = n0 + (lane & 3) * 2;
    #pragma unroll
    for (int nb = 0; nb < 8; nb++){
        *reinterpret_cast<float2*>(out + (size_t)row0 * NC + cb + nb * 8) =
            make_float2(o[nb][0], o[nb][1]);
        *reinterpret_cast<float2*>(out + (size_t)(row0 + 8) * NC + cb + nb * 8) =
            make_float2(o[nb][2], o[nb][3]);
    }
}

// ---------------------------------------------------------------------------
extern "C" void kernel_launch(void* const* d_in, const int* in_sizes, int n_in,
                              void* d_out, int out_size)
{
    const float* q = (const float*)d_in[0];
    const float* k = (const float*)d_in[1];
    const float* v = (const float*)d_in[2];
    const unsigned int* mask = (const unsigned int*)d_in[3];
    const float* W = (const float*)d_in[4];
    float* out = (float*)d_out;

    cudaFuncSetAttribute((const void*)attn_tc,
                         cudaFuncAttributeMaxDynamicSharedMemorySize, ASM_BYTES);
    cudaFuncSetAttribute((const void*)proj_tc,
                         cudaFuncAttributeMaxDynamicSharedMemorySize, PSM_BYTES);

    qkvconv<<<dim3(NS / 64, NH, NB), 256>>>(q, k, v);
    wconv<<<(NC * NC) / 256, 256>>>(W);
    biasconv<<<(NB * NS) / 256, 256>>>(mask);
    attn_tc<<<dim3(NS / BM, NH, NB), 256, ASM_BYTES>>>();
    proj_tc<<<dim3(NC / 64, (NB * NS) / 128), 256, PSM_BYTES>>>(out);
}

// round 5
// speedup vs baseline: 3.8285x; 1.3826x over previous
#include <cuda_runtime.h>
#include <cuda_bf16.h>
#include <cstdint>

#define NB 2
#define NS 2048
#define NC 1024
#define NH 16
#define ND 64
#define BM 64
#define BN 32
#define NTILE (NS/BN)   // 64

// ---- scratch (__device__ globals: allowed) ----
__device__ __nv_bfloat16 g_qhi[(size_t)NB*NH*NS*ND];
__device__ __nv_bfloat16 g_qlo[(size_t)NB*NH*NS*ND];
__device__ __nv_bfloat16 g_khi[(size_t)NB*NH*NS*ND];
__device__ __nv_bfloat16 g_klo[(size_t)NB*NH*NS*ND];
__device__ __nv_bfloat16 g_vthi[(size_t)NB*NH*ND*NS];  // V transposed [b,h,d,s]
__device__ __nv_bfloat16 g_vtlo[(size_t)NB*NH*ND*NS];
__device__ __nv_bfloat16 g_whi[(size_t)NC*NC];
__device__ __nv_bfloat16 g_wlo[(size_t)NC*NC];
__device__ __nv_bfloat16 g_ahi[(size_t)NB*NS*NC];
__device__ __nv_bfloat16 g_alo[(size_t)NB*NS*NC];
__device__ float g_bias[(size_t)NB*NS];

// ---------------- helpers ----------------
__device__ __forceinline__ uint32_t smem_u32(const void* p){
    uint32_t a;
    asm("{ .reg .u64 t; cvta.to.shared.u64 t, %1; cvt.u32.u64 %0, t; }"
        : "=r"(a) : "l"(p));
    return a;
}
#define SWZ(r, byte) ((uint32_t)((r)*128 + ((byte) ^ (((r)&7)<<4))))

__device__ __forceinline__ void cpa16(uint32_t dst, const void* src){
    asm volatile("cp.async.cg.shared.global [%0], [%1], 16;"
                 :: "r"(dst), "l"(src) : "memory");
}
#define CP_COMMIT() asm volatile("cp.async.commit_group;" ::: "memory")
#define CP_WAIT0()  asm volatile("cp.async.wait_group 0;" ::: "memory")

__device__ __forceinline__ void split2(float x, float y, uint32_t& hi, uint32_t& lo){
    __nv_bfloat162 h = __float22bfloat162_rn(make_float2(x, y));
    float2 hf = __bfloat1622float2(h);
    __nv_bfloat162 l = __float22bfloat162_rn(make_float2(x - hf.x, y - hf.y));
    hi = *reinterpret_cast<uint32_t*>(&h);
    lo = *reinterpret_cast<uint32_t*>(&l);
}
__device__ __forceinline__ void split4(float4 v, uint2& hi, uint2& lo){
    split2(v.x, v.y, hi.x, lo.x);
    split2(v.z, v.w, hi.y, lo.y);
}

__device__ __forceinline__ void ldsmA(uint32_t r[4], uint32_t region, int row0, int byte0){
    const int lane = threadIdx.x & 31;
    const int t = lane >> 3, rr = lane & 7;
    const int row = row0 + rr + ((t & 1) << 3);
    const int byte = byte0 + ((t >> 1) << 4);
    uint32_t addr = region + SWZ(row, byte);
    asm volatile("ldmatrix.sync.aligned.m8n8.x4.shared.b16 {%0,%1,%2,%3}, [%4];"
        : "=r"(r[0]), "=r"(r[1]), "=r"(r[2]), "=r"(r[3]) : "r"(addr));
}
__device__ __forceinline__ void ldsmB(uint32_t r[4], uint32_t region, int row0, int byte0){
    const int lane = threadIdx.x & 31;
    const int t = lane >> 3, rr = lane & 7;
    const int row = row0 + rr + ((t >> 1) << 3);
    const int byte = byte0 + ((t & 1) << 4);
    uint32_t addr = region + SWZ(row, byte);
    asm volatile("ldmatrix.sync.aligned.m8n8.x4.shared.b16 {%0,%1,%2,%3}, [%4];"
        : "=r"(r[0]), "=r"(r[1]), "=r"(r[2]), "=r"(r[3]) : "r"(addr));
}
__device__ __forceinline__ void mma16816(float c[4], const uint32_t a[4],
                                         uint32_t b0, uint32_t b1){
    asm volatile(
        "mma.sync.aligned.m16n8k16.row.col.f32.bf16.bf16.f32 "
        "{%0,%1,%2,%3}, {%4,%5,%6,%7}, {%8,%9}, {%0,%1,%2,%3};"
        : "+f"(c[0]), "+f"(c[1]), "+f"(c[2]), "+f"(c[3])
        : "r"(a[0]), "r"(a[1]), "r"(a[2]), "r"(a[3]), "r"(b0), "r"(b1));
}

// ===========================================================================
// Prepasses (unchanged from R4): Q/K -> hi/lo [b,h,s,d], V -> hi/lo [b,h,d,s],
// W -> hi/lo, mask -> additive bias.
// ===========================================================================
__global__ void __launch_bounds__(256) qkvconv(
    const float* __restrict__ q, const float* __restrict__ k,
    const float* __restrict__ v)
{
    __shared__ float sv[64][68];
    const int tid = threadIdx.x;
    const int b = blockIdx.z, h = blockIdx.y, s0 = blockIdx.x * 64;
    const size_t inb  = ((size_t)b * NS + s0) * NC + h * ND;
    const size_t outb = (((size_t)b * NH + h) * NS + s0) * ND;

    #pragma unroll
    for (int p = 0; p < 4; p++){
        int idx = tid + p * 256;
        int r = idx >> 4, c4 = idx & 15;
        size_t src = inb + (size_t)r * NC + c4 * 4;
        size_t dst = outb + r * ND + c4 * 4;
        float4 xq = *reinterpret_cast<const float4*>(q + src);
        xq.x *= 0.125f; xq.y *= 0.125f; xq.z *= 0.125f; xq.w *= 0.125f;
        uint2 hi, lo; split4(xq, hi, lo);
        *reinterpret_cast<uint2*>(g_qhi + dst) = hi;
        *reinterpret_cast<uint2*>(g_qlo + dst) = lo;
        float4 xk = *reinterpret_cast<const float4*>(k + src);
        split4(xk, hi, lo);
        *reinterpret_cast<uint2*>(g_khi + dst) = hi;
        *reinterpret_cast<uint2*>(g_klo + dst) = lo;
        float4 xv = *reinterpret_cast<const float4*>(v + src);
        *reinterpret_cast<float4*>(&sv[r][c4 * 4]) = xv;
    }
    __syncthreads();
    const int d = tid & 63, sh = (tid >> 6) * 16;
    uint32_t hi8[8], lo8[8];
    #pragma unroll
    for (int i = 0; i < 8; i++)
        split2(sv[sh + 2*i][d], sv[sh + 2*i + 1][d], hi8[i], lo8[i]);
    size_t voff = (((size_t)b * NH + h) * ND + d) * NS + s0 + sh;
    reinterpret_cast<uint4*>(g_vthi + voff)[0] = make_uint4(hi8[0],hi8[1],hi8[2],hi8[3]);
    reinterpret_cast<uint4*>(g_vthi + voff)[1] = make_uint4(hi8[4],hi8[5],hi8[6],hi8[7]);
    reinterpret_cast<uint4*>(g_vtlo + voff)[0] = make_uint4(lo8[0],lo8[1],lo8[2],lo8[3]);
    reinterpret_cast<uint4*>(g_vtlo + voff)[1] = make_uint4(lo8[4],lo8[5],lo8[6],lo8[7]);
}
__global__ void __launch_bounds__(256) wconv(const float* __restrict__ W){
    int i = blockIdx.x * 256 + threadIdx.x;
    float x = W[i];
    __nv_bfloat16 hi = __float2bfloat16_rn(x);
    g_whi[i] = hi;
    g_wlo[i] = __float2bfloat16_rn(x - __bfloat162float(hi));
}
__global__ void __launch_bounds__(256) biasconv(const unsigned int* __restrict__ mask){
    int i = blockIdx.x * 256 + threadIdx.x;
    g_bias[i] = (mask[i] != 0u) ? 0.0f : -1.0e12f;
}

// ---------------- attention smem (per CTA, bytes) ----------------
// Q: 64 rows x 128B, hi+lo. Then 2 pipeline stages of K/V/bias.
#define AQHI 0
#define AQLO 8192
#define ASTG0 16384
#define ASTG_STRIDE 25600
#define SK_HI 0
#define SK_LO 4096
#define SV_HI 8192
#define SV_LO 16384
#define SBIAS 24576
#define ASM_BYTES (ASTG0 + 2*ASTG_STRIDE)   // 67584

// ===========================================================================
// Attention: 128 threads = 4 warps; warp owns 16 q-rows x BN key-cols/tile,
// full ND=64 O columns. 3 CTAs/SM; cp.async double-buffered K/V.
// ===========================================================================
__global__ void __launch_bounds__(128, 3) attn_tc()
{
    extern __shared__ __align__(1024) char sm[];
    const uint32_t sb = smem_u32(sm);
    const int tid = threadIdx.x, lane = tid & 31, warp = tid >> 5;
    const int b = blockIdx.z, h = blockIdx.y, q0 = blockIdx.x * BM;

    const size_t qb  = (((size_t)b * NH + h) * NS + q0) * ND;
    const size_t kb  = ((size_t)b * NH + h) * NS * ND;
    const size_t vtb = ((size_t)b * NH + h) * (size_t)ND * NS;

    // ---- Q tile -> smem (hi+lo), once ----
    #pragma unroll
    for (int p = 0; p < 4; p++){
        int idx = tid + p * 128;             // 0..511
        int r = idx >> 3, ch = idx & 7;
        uint32_t off = SWZ(r, ch * 16);
        *reinterpret_cast<uint4*>(sm + AQHI + off) =
            *reinterpret_cast<const uint4*>(g_qhi + qb + (size_t)r * ND + ch * 8);
        *reinterpret_cast<uint4*>(sm + AQLO + off) =
            *reinterpret_cast<const uint4*>(g_qlo + qb + (size_t)r * ND + ch * 8);
    }
    __syncthreads();

    uint32_t qh[4][4], ql[4][4];
    #pragma unroll
    for (int kc = 0; kc < 4; kc++){
        ldsmA(qh[kc], sb + AQHI, warp * 16, kc * 32);
        ldsmA(ql[kc], sb + AQLO, warp * 16, kc * 32);
    }

    // ---- async tile loader (K 32x64, V 64x32, bias 32) ----
    auto load_tile = [&](int t, int stg){
        const int n0 = t * BN;
        const uint32_t st = sb + ASTG0 + stg * ASTG_STRIDE;
        #pragma unroll
        for (int p = 0; p < 4; p++){              // K hi+lo: 512 chunks
            int idx = tid + p * 128;
            int arr = idx >> 8, r = (idx >> 3) & 31, ch = idx & 7;
            const __nv_bfloat16* src = (arr ? g_klo : g_khi) + kb
                                     + (size_t)(n0 + r) * ND + ch * 8;
            cpa16(st + (arr ? SK_LO : SK_HI) + SWZ(r, ch * 16), src);
        }
        #pragma unroll
        for (int p = 0; p < 4; p++){              // V hi+lo: 512 chunks
            int idx = tid + p * 128;
            int arr = idx >> 8, r = (idx >> 2) & 63, ch = idx & 3;
            const __nv_bfloat16* src = (arr ? g_vtlo : g_vthi) + vtb
                                     + (size_t)r * NS + n0 + ch * 8;
            cpa16(st + (arr ? SV_LO : SV_HI) + SWZ(r, ch * 16), src);
        }
        if (tid < 8)
            cpa16(st + SBIAS + tid * 16, g_bias + (size_t)b * NS + n0 + tid * 4);
        CP_COMMIT();
    };

    float o[8][4] = {};
    float lsum0 = 0.f, lsum1 = 0.f;

    load_tile(0, 0);

    #pragma unroll 1
    for (int t = 0; t < NTILE; t++){
        CP_WAIT0();
        __syncthreads();
        if (t + 1 < NTILE) load_tile(t + 1, (t + 1) & 1);

        const uint32_t st = sb + ASTG0 + (t & 1) * ASTG_STRIDE;
        const float* biasf = reinterpret_cast<const float*>(sm + (st - sb) + SBIAS);

        // ---- GEMM1: S = Qhi*Khi + Qhi*Klo + Qlo*Khi ----
        float s[4][4] = {};
        #pragma unroll
        for (int term = 0; term < 3; term++){
            const uint32_t (*A)[4] = (term == 2) ? ql : qh;
            const uint32_t reg = st + ((term == 1) ? SK_LO : SK_HI);
            #pragma unroll
            for (int kc = 0; kc < 4; kc++){
                #pragma unroll
                for (int nbp = 0; nbp < 2; nbp++){
                    uint32_t bf[4];
                    ldsmB(bf, reg, nbp * 16, kc * 32);
                    mma16816(s[nbp * 2],     A[kc], bf[0], bf[1]);
                    mma16816(s[nbp * 2 + 1], A[kc], bf[2], bf[3]);
                }
            }
        }

        // ---- softmax in registers + split-bf16 pack into A-frags ----
        uint32_t ph[2][4], pl[2][4];
        #pragma unroll
        for (int nb = 0; nb < 4; nb++){
            float2 b2 = *reinterpret_cast<const float2*>(
                biasf + nb * 8 + (lane & 3) * 2);
            float e0 = __expf(s[nb][0] + b2.x);
            float e1 = __expf(s[nb][1] + b2.y);
            float e2 = __expf(s[nb][2] + b2.x);
            float e3 = __expf(s[nb][3] + b2.y);
            lsum0 += e0 + e1;
            lsum1 += e2 + e3;
            split2(e0, e1, ph[nb >> 1][(nb & 1) * 2 + 0], pl[nb >> 1][(nb & 1) * 2 + 0]);
            split2(e2, e3, ph[nb >> 1][(nb & 1) * 2 + 1], pl[nb >> 1][(nb & 1) * 2 + 1]);
        }

        // ---- GEMM2: O += Phi*Vhi + Phi*Vlo + Plo*Vhi ----
        #pragma unroll
        for (int term = 0; term < 3; term++){
            const uint32_t (*A)[4] = (term == 2) ? pl : ph;
            const uint32_t reg = st + ((term == 1) ? SV_LO : SV_HI);
            #pragma unroll
            for (int kc = 0; kc < 2; kc++){
                #pragma unroll
                for (int nbp = 0; nbp < 4; nbp++){
                    uint32_t bf[4];
                    ldsmB(bf, reg, nbp * 16, kc * 32);
                    mma16816(o[nbp * 2],     A[kc], bf[0], bf[1]);
                    mma16816(o[nbp * 2 + 1], A[kc], bf[2], bf[3]);
                }
            }
        }
    }

    lsum0 += __shfl_xor_sync(0xffffffffu, lsum0, 1);
    lsum0 += __shfl_xor_sync(0xffffffffu, lsum0, 2);
    lsum1 += __shfl_xor_sync(0xffffffffu, lsum1, 1);
    lsum1 += __shfl_xor_sync(0xffffffffu, lsum1, 2);
    const float inv0 = 1.0f / lsum0, inv1 = 1.0f / lsum1;

    const int row0 = q0 + warp * 16 + (lane >> 2);
    const int cbase = h * ND + (lane & 3) * 2;
    #pragma unroll
    for (int nb = 0; nb < 8; nb++){
        uint32_t hi, lo;
        size_t off0 = ((size_t)b * NS + row0) * NC + cbase + nb * 8;
        split2(o[nb][0] * inv0, o[nb][1] * inv0, hi, lo);
        *reinterpret_cast<uint32_t*>(g_ahi + off0) = hi;
        *reinterpret_cast<uint32_t*>(g_alo + off0) = lo;
        size_t off1 = off0 + (size_t)8 * NC;
        split2(o[nb][2] * inv1, o[nb][3] * inv1, hi, lo);
        *reinterpret_cast<uint32_t*>(g_ahi + off1) = hi;
        *reinterpret_cast<uint32_t*>(g_alo + off1) = lo;
    }
}

// ---------------- projection smem (per CTA, 2 stages x 48KB) ----------------
#define PSTG_STRIDE 49152
#define PA_HI 0
#define PA_LO 16384
#define PW_HI 32768
#define PW_LO 40960
#define PSM_BYTES (2*PSTG_STRIDE)   // 96KB

// ===========================================================================
// Projection: 128 m x 64 n tile, k in 16 chunks of 64, cp.async 2-stage.
// ===========================================================================
__global__ void __launch_bounds__(256, 2) proj_tc(float* __restrict__ out)
{
    extern __shared__ __align__(1024) char sm[];
    const uint32_t sb = smem_u32(sm);
    const int tid = threadIdx.x, lane = tid & 31, warp = tid >> 5;
    const int n0 = blockIdx.x * 64, m0 = blockIdx.y * 128;

    auto load_chunk = [&](int kc_o, int stg){
        const int k0 = kc_o * 64;
        const uint32_t st = sb + stg * PSTG_STRIDE;
        #pragma unroll
        for (int p = 0; p < 8; p++){              // A hi+lo: 2048 chunks
            int idx = tid + p * 256;
            int arr = idx >> 10, r = (idx >> 3) & 127, ch = idx & 7;
            const __nv_bfloat16* src = (arr ? g_alo : g_ahi)
                + (size_t)(m0 + r) * NC + k0 + ch * 8;
            cpa16(st + (arr ? PA_LO : PA_HI) + SWZ(r, ch * 16), src);
        }
        #pragma unroll
        for (int p = 0; p < 4; p++){              // W hi+lo: 1024 chunks
            int idx = tid + p * 256;
            int arr = idx >> 9, r = (idx >> 3) & 63, ch = idx & 7;
            const __nv_bfloat16* src = (arr ? g_wlo : g_whi)
                + (size_t)(n0 + r) * NC + k0 + ch * 8;
            cpa16(st + (arr ? PW_LO : PW_HI) + SWZ(r, ch * 16), src);
        }
        CP_COMMIT();
    };

    float o[8][4] = {};
    load_chunk(0, 0);

    #pragma unroll 1
    for (int kc_o = 0; kc_o < 16; kc_o++){
        CP_WAIT0();
        __syncthreads();
        if (kc_o + 1 < 16) load_chunk(kc_o + 1, (kc_o + 1) & 1);

        const uint32_t st = sb + (kc_o & 1) * PSTG_STRIDE;
        uint32_t ah[4][4], al[4][4];
        #pragma unroll
        for (int kc = 0; kc < 4; kc++){
            ldsmA(ah[kc], st + PA_HI, warp * 16, kc * 32);
            ldsmA(al[kc], st + PA_LO, warp * 16, kc * 32);
        }
        #pragma unroll
        for (int term = 0; term < 3; term++){
            const uint32_t (*A)[4] = (term == 2) ? al : ah;
            const uint32_t reg = st + ((term == 1) ? PW_LO : PW_HI);
            #pragma unroll
            for (int kc = 0; kc < 4; kc++){
                #pragma unroll
                for (int nbp = 0; nbp < 4; nbp++){
                    uint32_t bf[4];
                    ldsmB(bf, reg, nbp * 16, kc * 32);
                    mma16816(o[nbp * 2],     A[kc], bf[0], bf[1]);
                    mma16816(o[nbp * 2 + 1], A[kc], bf[2], bf[3]);
                }
            }
        }
    }

    const int row0 = m0 + warp * 16 + (lane >> 2);
    const int cb = n0 + (lane & 3) * 2;
    #pragma unroll
    for (int nb = 0; nb < 8; nb++){
        *reinterpret_cast<float2*>(out + (size_t)row0 * NC + cb + nb * 8) =
            make_float2(o[nb][0], o[nb][1]);
        *reinterpret_cast<float2*>(out + (size_t)(row0 + 8) * NC + cb + nb * 8) =
            make_float2(o[nb][2], o[nb][3]);
    }
}

// ---------------------------------------------------------------------------
extern "C" void kernel_launch(void* const* d_in, const int* in_sizes, int n_in,
                              void* d_out, int out_size)
{
    const float* q = (const float*)d_in[0];
    const float* k = (const float*)d_in[1];
    const float* v = (const float*)d_in[2];
    const unsigned int* mask = (const unsigned int*)d_in[3];
    const float* W = (const float*)d_in[4];
    float* out = (float*)d_out;

    cudaFuncSetAttribute((const void*)attn_tc,
                         cudaFuncAttributeMaxDynamicSharedMemorySize, ASM_BYTES);
    cudaFuncSetAttribute((const void*)proj_tc,
                         cudaFuncAttributeMaxDynamicSharedMemorySize, PSM_BYTES);

    qkvconv<<<dim3(NS / 64, NH, NB), 256>>>(q, k, v);
    wconv<<<(NC * NC) / 256, 256>>>(W);
    biasconv<<<(NB * NS) / 256, 256>>>(mask);
    attn_tc<<<dim3(NS / BM, NH, NB), 128, ASM_BYTES>>>();
    proj_tc<<<dim3(NC / 64, (NB * NS) / 128), 256, PSM_BYTES>>>(out);
}

// round 7
// speedup vs baseline: 4.1524x; 1.0846x over previous
#include <cuda_runtime.h>
#include <cuda_bf16.h>
#include <cstdint>

#define NB 2
#define NS 2048
#define NC 1024
#define NH 16
#define ND 64
#define BM 64
#define BN 32
#define NTILE (NS/BN)   // 64

// ---- scratch (__device__ globals: allowed) ----
__device__ __nv_bfloat16 g_qhi[(size_t)NB*NH*NS*ND];
__device__ __nv_bfloat16 g_qlo[(size_t)NB*NH*NS*ND];
__device__ __nv_bfloat16 g_khi[(size_t)NB*NH*NS*ND];
__device__ __nv_bfloat16 g_klo[(size_t)NB*NH*NS*ND];
__device__ __nv_bfloat16 g_vthi[(size_t)NB*NH*ND*NS];  // V transposed [b,h,d,s]
__device__ __nv_bfloat16 g_vtlo[(size_t)NB*NH*ND*NS];
__device__ __nv_bfloat16 g_whi[(size_t)NC*NC];
__device__ __nv_bfloat16 g_wlo[(size_t)NC*NC];
__device__ __nv_bfloat16 g_ahi[(size_t)NB*NS*NC];
__device__ __nv_bfloat16 g_alo[(size_t)NB*NS*NC];
__device__ float g_bias[(size_t)NB*NS];

// ---------------- helpers ----------------
__device__ __forceinline__ uint32_t smem_u32(const void* p){
    uint32_t a;
    asm("{ .reg .u64 t; cvta.to.shared.u64 t, %1; cvt.u32.u64 %0, t; }"
        : "=r"(a) : "l"(p));
    return a;
}
#define SWZ(r, byte) ((uint32_t)((r)*128 + ((byte) ^ (((r)&7)<<4))))

__device__ __forceinline__ void cpa16(uint32_t dst, const void* src){
    asm volatile("cp.async.cg.shared.global [%0], [%1], 16;"
                 :: "r"(dst), "l"(src) : "memory");
}
#define CP_COMMIT() asm volatile("cp.async.commit_group;" ::: "memory")
#define CP_WAIT0()  asm volatile("cp.async.wait_group 0;" ::: "memory")

__device__ __forceinline__ void split2(float x, float y, uint32_t& hi, uint32_t& lo){
    __nv_bfloat162 h = __float22bfloat162_rn(make_float2(x, y));
    float2 hf = __bfloat1622float2(h);
    __nv_bfloat162 l = __float22bfloat162_rn(make_float2(x - hf.x, y - hf.y));
    hi = *reinterpret_cast<uint32_t*>(&h);
    lo = *reinterpret_cast<uint32_t*>(&l);
}
__device__ __forceinline__ void split4(float4 v, uint2& hi, uint2& lo){
    split2(v.x, v.y, hi.x, lo.x);
    split2(v.z, v.w, hi.y, lo.y);
}

__device__ __forceinline__ void ldsmA(uint32_t r[4], uint32_t region, int row0, int byte0){
    const int lane = threadIdx.x & 31;
    const int t = lane >> 3, rr = lane & 7;
    const int row = row0 + rr + ((t & 1) << 3);
    const int byte = byte0 + ((t >> 1) << 4);
    uint32_t addr = region + SWZ(row, byte);
    asm volatile("ldmatrix.sync.aligned.m8n8.x4.shared.b16 {%0,%1,%2,%3}, [%4];"
        : "=r"(r[0]), "=r"(r[1]), "=r"(r[2]), "=r"(r[3]) : "r"(addr));
}
__device__ __forceinline__ void ldsmB(uint32_t r[4], uint32_t region, int row0, int byte0){
    const int lane = threadIdx.x & 31;
    const int t = lane >> 3, rr = lane & 7;
    const int row = row0 + rr + ((t >> 1) << 3);
    const int byte = byte0 + ((t & 1) << 4);
    uint32_t addr = region + SWZ(row, byte);
    asm volatile("ldmatrix.sync.aligned.m8n8.x4.shared.b16 {%0,%1,%2,%3}, [%4];"
        : "=r"(r[0]), "=r"(r[1]), "=r"(r[2]), "=r"(r[3]) : "r"(addr));
}
__device__ __forceinline__ void mma16816(float c[4], const uint32_t a[4],
                                         uint32_t b0, uint32_t b1){
    asm volatile(
        "mma.sync.aligned.m16n8k16.row.col.f32.bf16.bf16.f32 "
        "{%0,%1,%2,%3}, {%4,%5,%6,%7}, {%8,%9}, {%0,%1,%2,%3};"
        : "+f"(c[0]), "+f"(c[1]), "+f"(c[2]), "+f"(c[3])
        : "r"(a[0]), "r"(a[1]), "r"(a[2]), "r"(a[3]), "r"(b0), "r"(b1));
}

// ===========================================================================
// Prepasses: Q/K -> hi/lo [b,h,s,d], V -> hi/lo [b,h,d,s], W -> hi/lo,
// mask -> additive bias.
// ===========================================================================
__global__ void __launch_bounds__(256) qkvconv(
    const float* __restrict__ q, const float* __restrict__ k,
    const float* __restrict__ v)
{
    __shared__ float sv[64][68];
    const int tid = threadIdx.x;
    const int b = blockIdx.z, h = blockIdx.y, s0 = blockIdx.x * 64;
    const size_t inb  = ((size_t)b * NS + s0) * NC + h * ND;
    const size_t outb = (((size_t)b * NH + h) * NS + s0) * ND;

    #pragma unroll
    for (int p = 0; p < 4; p++){
        int idx = tid + p * 256;
        int r = idx >> 4, c4 = idx & 15;
        size_t src = inb + (size_t)r * NC + c4 * 4;
        size_t dst = outb + r * ND + c4 * 4;
        float4 xq = *reinterpret_cast<const float4*>(q + src);
        xq.x *= 0.125f; xq.y *= 0.125f; xq.z *= 0.125f; xq.w *= 0.125f;
        uint2 hi, lo; split4(xq, hi, lo);
        *reinterpret_cast<uint2*>(g_qhi + dst) = hi;
        *reinterpret_cast<uint2*>(g_qlo + dst) = lo;
        float4 xk = *reinterpret_cast<const float4*>(k + src);
        split4(xk, hi, lo);
        *reinterpret_cast<uint2*>(g_khi + dst) = hi;
        *reinterpret_cast<uint2*>(g_klo + dst) = lo;
        float4 xv = *reinterpret_cast<const float4*>(v + src);
        *reinterpret_cast<float4*>(&sv[r][c4 * 4]) = xv;
    }
    __syncthreads();
    const int d = tid & 63, sh = (tid >> 6) * 16;
    uint32_t hi8[8], lo8[8];
    #pragma unroll
    for (int i = 0; i < 8; i++)
        split2(sv[sh + 2*i][d], sv[sh + 2*i + 1][d], hi8[i], lo8[i]);
    size_t voff = (((size_t)b * NH + h) * ND + d) * NS + s0 + sh;
    reinterpret_cast<uint4*>(g_vthi + voff)[0] = make_uint4(hi8[0],hi8[1],hi8[2],hi8[3]);
    reinterpret_cast<uint4*>(g_vthi + voff)[1] = make_uint4(hi8[4],hi8[5],hi8[6],hi8[7]);
    reinterpret_cast<uint4*>(g_vtlo + voff)[0] = make_uint4(lo8[0],lo8[1],lo8[2],lo8[3]);
    reinterpret_cast<uint4*>(g_vtlo + voff)[1] = make_uint4(lo8[4],lo8[5],lo8[6],lo8[7]);
}
__global__ void __launch_bounds__(256) wconv(const float* __restrict__ W){
    int i = blockIdx.x * 256 + threadIdx.x;
    float x = W[i];
    __nv_bfloat16 hi = __float2bfloat16_rn(x);
    g_whi[i] = hi;
    g_wlo[i] = __float2bfloat16_rn(x - __bfloat162float(hi));
}
__global__ void __launch_bounds__(256) biasconv(const unsigned int* __restrict__ mask){
    int i = blockIdx.x * 256 + threadIdx.x;
    g_bias[i] = (mask[i] != 0u) ? 0.0f : -1.0e12f;
}

// ---------------- attention smem (per CTA, bytes) ----------------
#define AQHI 0
#define AQLO 8192
#define ASTG0 16384
#define ASTG_STRIDE 25600
#define SK_HI 0
#define SK_LO 4096
#define SV_HI 8192
#define SV_LO 16384
#define SBIAS 24576
#define ASM_BYTES (ASTG0 + 2*ASTG_STRIDE)   // 67584

// ===========================================================================
// Attention: 128 threads = 4 warps; 3 CTAs/SM; cp.async double-buffered K/V.
// Inner loops are term-innermost: B-frags (hi+lo) loaded ONCE per (kc,nbp),
// all 3 split-product MMAs issued against them (16 ldsmB / GEMM / tile).
// ===========================================================================
__global__ void __launch_bounds__(128, 3) attn_tc()
{
    extern __shared__ __align__(1024) char sm[];
    const uint32_t sb = smem_u32(sm);
    const int tid = threadIdx.x, lane = tid & 31, warp = tid >> 5;
    const int b = blockIdx.z, h = blockIdx.y, q0 = blockIdx.x * BM;

    const size_t qb  = (((size_t)b * NH + h) * NS + q0) * ND;
    const size_t kb  = ((size_t)b * NH + h) * NS * ND;
    const size_t vtb = ((size_t)b * NH + h) * (size_t)ND * NS;

    // ---- Q tile -> smem (hi+lo), once ----
    #pragma unroll
    for (int p = 0; p < 4; p++){
        int idx = tid + p * 128;             // 0..511
        int r = idx >> 3, ch = idx & 7;
        uint32_t off = SWZ(r, ch * 16);
        *reinterpret_cast<uint4*>(sm + AQHI + off) =
            *reinterpret_cast<const uint4*>(g_qhi + qb + (size_t)r * ND + ch * 8);
        *reinterpret_cast<uint4*>(sm + AQLO + off) =
            *reinterpret_cast<const uint4*>(g_qlo + qb + (size_t)r * ND + ch * 8);
    }
    __syncthreads();

    uint32_t qh[4][4], ql[4][4];
    #pragma unroll
    for (int kc = 0; kc < 4; kc++){
        ldsmA(qh[kc], sb + AQHI, warp * 16, kc * 32);
        ldsmA(ql[kc], sb + AQLO, warp * 16, kc * 32);
    }

    // ---- async tile loader (K 32x64, V 64x32, bias 32) ----
    auto load_tile = [&](int t, int stg){
        const int n0 = t * BN;
        const uint32_t st = sb + ASTG0 + stg * ASTG_STRIDE;
        #pragma unroll
        for (int p = 0; p < 4; p++){              // K hi+lo: 512 chunks
            int idx = tid + p * 128;
            int arr = idx >> 8, r = (idx >> 3) & 31, ch = idx & 7;
            const __nv_bfloat16* src = (arr ? g_klo : g_khi) + kb
                                     + (size_t)(n0 + r) * ND + ch * 8;
            cpa16(st + (arr ? SK_LO : SK_HI) + SWZ(r, ch * 16), src);
        }
        #pragma unroll
        for (int p = 0; p < 4; p++){              // V hi+lo: 512 chunks
            int idx = tid + p * 128;
            int arr = idx >> 8, r = (idx >> 2) & 63, ch = idx & 3;
            const __nv_bfloat16* src = (arr ? g_vtlo : g_vthi) + vtb
                                     + (size_t)r * NS + n0 + ch * 8;
            cpa16(st + (arr ? SV_LO : SV_HI) + SWZ(r, ch * 16), src);
        }
        if (tid < 8)
            cpa16(st + SBIAS + tid * 16, g_bias + (size_t)b * NS + n0 + tid * 4);
        CP_COMMIT();
    };

    float o[8][4] = {};
    float lsum0 = 0.f, lsum1 = 0.f;

    load_tile(0, 0);

    #pragma unroll 1
    for (int t = 0; t < NTILE; t++){
        CP_WAIT0();
        __syncthreads();
        if (t + 1 < NTILE) load_tile(t + 1, (t + 1) & 1);

        const uint32_t st = sb + ASTG0 + (t & 1) * ASTG_STRIDE;
        const float* biasf = reinterpret_cast<const float*>(sm + (st - sb) + SBIAS);

        // ---- GEMM1: S = Qhi*Khi + Qhi*Klo + Qlo*Khi (B-frag reuse) ----
        float s[4][4] = {};
        #pragma unroll
        for (int kc = 0; kc < 4; kc++){
            #pragma unroll
            for (int nbp = 0; nbp < 2; nbp++){
                uint32_t bh[4], bl[4];
                ldsmB(bh, st + SK_HI, nbp * 16, kc * 32);
                ldsmB(bl, st + SK_LO, nbp * 16, kc * 32);
                mma16816(s[nbp * 2],     qh[kc], bh[0], bh[1]);
                mma16816(s[nbp * 2 + 1], qh[kc], bh[2], bh[3]);
                mma16816(s[nbp * 2],     qh[kc], bl[0], bl[1]);
                mma16816(s[nbp * 2 + 1], qh[kc], bl[2], bl[3]);
                mma16816(s[nbp * 2],     ql[kc], bh[0], bh[1]);
                mma16816(s[nbp * 2 + 1], ql[kc], bh[2], bh[3]);
            }
        }

        // ---- softmax in registers + split-bf16 pack into A-frags ----
        uint32_t ph[2][4], pl[2][4];
        #pragma unroll
        for (int nb = 0; nb < 4; nb++){
            float2 b2 = *reinterpret_cast<const float2*>(
                biasf + nb * 8 + (lane & 3) * 2);
            float e0 = __expf(s[nb][0] + b2.x);
            float e1 = __expf(s[nb][1] + b2.y);
            float e2 = __expf(s[nb][2] + b2.x);
            float e3 = __expf(s[nb][3] + b2.y);
            lsum0 += e0 + e1;
            lsum1 += e2 + e3;
            split2(e0, e1, ph[nb >> 1][(nb & 1) * 2 + 0], pl[nb >> 1][(nb & 1) * 2 + 0]);
            split2(e2, e3, ph[nb >> 1][(nb & 1) * 2 + 1], pl[nb >> 1][(nb & 1) * 2 + 1]);
        }

        // ---- GEMM2: O += Phi*Vhi + Phi*Vlo + Plo*Vhi (B-frag reuse) ----
        #pragma unroll
        for (int kc = 0; kc < 2; kc++){
            #pragma unroll
            for (int nbp = 0; nbp < 4; nbp++){
                uint32_t bh[4], bl[4];
                ldsmB(bh, st + SV_HI, nbp * 16, kc * 32);
                ldsmB(bl, st + SV_LO, nbp * 16, kc * 32);
                mma16816(o[nbp * 2],     ph[kc], bh[0], bh[1]);
                mma16816(o[nbp * 2 + 1], ph[kc], bh[2], bh[3]);
                mma16816(o[nbp * 2],     ph[kc], bl[0], bl[1]);
                mma16816(o[nbp * 2 + 1], ph[kc], bl[2], bl[3]);
                mma16816(o[nbp * 2],     pl[kc], bh[0], bh[1]);
                mma16816(o[nbp * 2 + 1], pl[kc], bh[2], bh[3]);
            }
        }
    }

    lsum0 += __shfl_xor_sync(0xffffffffu, lsum0, 1);
    lsum0 += __shfl_xor_sync(0xffffffffu, lsum0, 2);
    lsum1 += __shfl_xor_sync(0xffffffffu, lsum1, 1);
    lsum1 += __shfl_xor_sync(0xffffffffu, lsum1, 2);
    const float inv0 = 1.0f / lsum0, inv1 = 1.0f / lsum1;

    const int row0 = q0 + warp * 16 + (lane >> 2);
    const int cbase = h * ND + (lane & 3) * 2;
    #pragma unroll
    for (int nb = 0; nb < 8; nb++){
        uint32_t hi, lo;
        size_t off0 = ((size_t)b * NS + row0) * NC + cbase + nb * 8;
        split2(o[nb][0] * inv0, o[nb][1] * inv0, hi, lo);
        *reinterpret_cast<uint32_t*>(g_ahi + off0) = hi;
        *reinterpret_cast<uint32_t*>(g_alo + off0) = lo;
        size_t off1 = off0 + (size_t)8 * NC;
        split2(o[nb][2] * inv1, o[nb][3] * inv1, hi, lo);
        *reinterpret_cast<uint32_t*>(g_ahi + off1) = hi;
        *reinterpret_cast<uint32_t*>(g_alo + off1) = lo;
    }
}

// ---------------- projection smem (per CTA, 2 stages x 48KB) ----------------
#define PSTG_STRIDE 49152
#define PA_HI 0
#define PA_LO 16384
#define PW_HI 32768
#define PW_LO 40960
#define PSM_BYTES (2*PSTG_STRIDE)   // 96KB

// ===========================================================================
// Projection: 128 m x 64 n tile, k in 16 chunks of 64, cp.async 2-stage,
// term-innermost B-frag reuse.
// ===========================================================================
__global__ void __launch_bounds__(256, 2) proj_tc(float* __restrict__ out)
{
    extern __shared__ __align__(1024) char sm[];
    const uint32_t sb = smem_u32(sm);
    const int tid = threadIdx.x, lane = tid & 31, warp = tid >> 5;
    const int n0 = blockIdx.x * 64, m0 = blockIdx.y * 128;

    auto load_chunk = [&](int kc_o, int stg){
        const int k0 = kc_o * 64;
        const uint32_t st = sb + stg * PSTG_STRIDE;
        #pragma unroll
        for (int p = 0; p < 8; p++){              // A hi+lo: 2048 chunks
            int idx = tid + p * 256;
            int arr = idx >> 10, r = (idx >> 3) & 127, ch = idx & 7;
            const __nv_bfloat16* src = (arr ? g_alo : g_ahi)
                + (size_t)(m0 + r) * NC + k0 + ch * 8;
            cpa16(st + (arr ? PA_LO : PA_HI) + SWZ(r, ch * 16), src);
        }
        #pragma unroll
        for (int p = 0; p < 4; p++){              // W hi+lo: 1024 chunks
            int idx = tid + p * 256;
            int arr = idx >> 9, r = (idx >> 3) & 63, ch = idx & 7;
            const __nv_bfloat16* src = (arr ? g_wlo : g_whi)
                + (size_t)(n0 + r) * NC + k0 + ch * 8;
            cpa16(st + (arr ? PW_LO : PW_HI) + SWZ(r, ch * 16), src);
        }
        CP_COMMIT();
    };

    float o[8][4] = {};
    load_chunk(0, 0);

    #pragma unroll 1
    for (int kc_o = 0; kc_o < 16; kc_o++){
        CP_WAIT0();
        __syncthreads();
        if (kc_o + 1 < 16) load_chunk(kc_o + 1, (kc_o + 1) & 1);

        const uint32_t st = sb + (kc_o & 1) * PSTG_STRIDE;
        uint32_t ah[4][4], al[4][4];
        #pragma unroll
        for (int kc = 0; kc < 4; kc++){
            ldsmA(ah[kc], st + PA_HI, warp * 16, kc * 32);
            ldsmA(al[kc], st + PA_LO, warp * 16, kc * 32);
        }
        #pragma unroll
        for (int kc = 0; kc < 4; kc++){
            #pragma unroll
            for (int nbp = 0; nbp < 4; nbp++){
                uint32_t bh[4], bl[4];
                ldsmB(bh, st + PW_HI, nbp * 16, kc * 32);
                ldsmB(bl, st + PW_LO, nbp * 16, kc * 32);
                mma16816(o[nbp * 2],     ah[kc], bh[0], bh[1]);
                mma16816(o[nbp * 2 + 1], ah[kc], bh[2], bh[3]);
                mma16816(o[nbp * 2],     ah[kc], bl[0], bl[1]);
                mma16816(o[nbp * 2 + 1], ah[kc], bl[2], bl[3]);
                mma16816(o[nbp * 2],     al[kc], bh[0], bh[1]);
                mma16816(o[nbp * 2 + 1], al[kc], bh[2], bh[3]);
            }
        }
    }

    const int row0 = m0 + warp * 16 + (lane >> 2);
    const int cb = n0 + (lane & 3) * 2;
    #pragma unroll
    for (int nb = 0; nb < 8; nb++){
        *reinterpret_cast<float2*>(out + (size_t)row0 * NC + cb + nb * 8) =
            make_float2(o[nb][0], o[nb][1]);
        *reinterpret_cast<float2*>(out + (size_t)(row0 + 8) * NC + cb + nb * 8) =
            make_float2(o[nb][2], o[nb][3]);
    }
}

// ---------------------------------------------------------------------------
extern "C" void kernel_launch(void* const* d_in, const int* in_sizes, int n_in,
                              void* d_out, int out_size)
{
    const float* q = (const float*)d_in[0];
    const float* k = (const float*)d_in[1];
    const float* v = (const float*)d_in[2];
    const unsigned int* mask = (const unsigned int*)d_in[3];
    const float* W = (const float*)d_in[4];
    float* out = (float*)d_out;

    cudaFuncSetAttribute((const void*)attn_tc,
                         cudaFuncAttributeMaxDynamicSharedMemorySize, ASM_BYTES);
    cudaFuncSetAttribute((const void*)proj_tc,
                         cudaFuncAttributeMaxDynamicSharedMemorySize, PSM_BYTES);

    qkvconv<<<dim3(NS / 64, NH, NB), 256>>>(q, k, v);
    wconv<<<(NC * NC) / 256, 256>>>(W);
    biasconv<<<(NB * NS) / 256, 256>>>(mask);
    attn_tc<<<dim3(NS / BM, NH, NB), 128, ASM_BYTES>>>();
    proj_tc<<<dim3(NC / 64, (NB * NS) / 128), 256, PSM_BYTES>>>(out);
}